// round 3
// baseline (speedup 1.0000x reference)
#include <cuda_runtime.h>
#include <math.h>

#define EMBED 768
#define NH    12
#define HD    64
#define BATCH 4
#define SEQ   2048
#define MROWS (BATCH*SEQ)   // 8192

// Scratch (no allocations allowed): head-split Q/K/V and attention context.
__device__ float g_q[BATCH*NH*SEQ*HD];
__device__ float g_k[BATCH*NH*SEQ*HD];
__device__ float g_v[BATCH*NH*SEQ*HD];
__device__ float g_ctx[MROWS*EMBED];

// ---------------------------------------------------------------------------
// GEMM: C[m,c] = sum_k A[m,k] * W[c,k]  (+bias)  -- "NT" layout, K=768
// 128x128 block tile, BK=16, 256 threads, 8x8 register microtile.
// ---------------------------------------------------------------------------
#define BM 128
#define BN 128
#define BK 16

__device__ __forceinline__ void gemm_mainloop(const float* __restrict__ A,
                                              const float* __restrict__ W,
                                              int m0, int n0, float acc[8][8])
{
    __shared__ float As[BK][BM];
    __shared__ float Bs[BK][BN];

    const int tid = threadIdx.x;
    const int lr  = tid >> 1;          // 0..127 (tile row for loads)
    const int lc  = (tid & 1) << 3;    // 0 or 8 (k offset for loads)
    const int ty  = tid >> 4;          // 0..15
    const int tx  = tid & 15;          // 0..15

    const float* Aptr = A + (m0 + lr) * EMBED + lc;
    const float* Wptr = W + (n0 + lr) * EMBED + lc;

    float4 a0 = *(const float4*)(Aptr + 0);
    float4 a1 = *(const float4*)(Aptr + 4);
    float4 b0 = *(const float4*)(Wptr + 0);
    float4 b1 = *(const float4*)(Wptr + 4);

    #pragma unroll 1
    for (int k0 = 0; k0 < EMBED; k0 += BK) {
        __syncthreads();
        As[lc+0][lr]=a0.x; As[lc+1][lr]=a0.y; As[lc+2][lr]=a0.z; As[lc+3][lr]=a0.w;
        As[lc+4][lr]=a1.x; As[lc+5][lr]=a1.y; As[lc+6][lr]=a1.z; As[lc+7][lr]=a1.w;
        Bs[lc+0][lr]=b0.x; Bs[lc+1][lr]=b0.y; Bs[lc+2][lr]=b0.z; Bs[lc+3][lr]=b0.w;
        Bs[lc+4][lr]=b1.x; Bs[lc+5][lr]=b1.y; Bs[lc+6][lr]=b1.z; Bs[lc+7][lr]=b1.w;
        __syncthreads();

        if (k0 + BK < EMBED) {        // prefetch next slab into registers
            a0 = *(const float4*)(Aptr + k0 + BK + 0);
            a1 = *(const float4*)(Aptr + k0 + BK + 4);
            b0 = *(const float4*)(Wptr + k0 + BK + 0);
            b1 = *(const float4*)(Wptr + k0 + BK + 4);
        }

        #pragma unroll
        for (int k = 0; k < BK; k++) {
            float a[8], b[8];
            *(float4*)(a)   = *(const float4*)&As[k][ty*8];
            *(float4*)(a+4) = *(const float4*)&As[k][ty*8+4];
            *(float4*)(b)   = *(const float4*)&Bs[k][tx*8];
            *(float4*)(b+4) = *(const float4*)&Bs[k][tx*8+4];
            #pragma unroll
            for (int i = 0; i < 8; i++)
                #pragma unroll
                for (int j = 0; j < 8; j++)
                    acc[i][j] += a[i]*b[j];
        }
    }
}

// QKV projections: grid.z in {0,1,2} selects Q/K/V; writes head-split layout
// dst[((b*NH+h)*SEQ + n)*HD + d]
__global__ __launch_bounds__(256) void qkv_gemm_kernel(
    const float* __restrict__ x,
    const float* __restrict__ Wq, const float* __restrict__ bq,
    const float* __restrict__ Wk, const float* __restrict__ bk,
    const float* __restrict__ Wv, const float* __restrict__ bv)
{
    const float* W; const float* bias; float* dst;
    if (blockIdx.z == 0)      { W = Wq; bias = bq; dst = g_q; }
    else if (blockIdx.z == 1) { W = Wk; bias = bk; dst = g_k; }
    else                      { W = Wv; bias = bv; dst = g_v; }

    const int m0 = blockIdx.y * BM;
    const int n0 = blockIdx.x * BN;

    float acc[8][8];
    #pragma unroll
    for (int i = 0; i < 8; i++)
        #pragma unroll
        for (int j = 0; j < 8; j++) acc[i][j] = 0.f;

    gemm_mainloop(x, W, m0, n0, acc);

    const int ty = threadIdx.x >> 4, tx = threadIdx.x & 15;
    #pragma unroll
    for (int i = 0; i < 8; i++) {
        const int m = m0 + ty*8 + i;
        const int b = m >> 11;          // /2048
        const int n = m & 2047;
        #pragma unroll
        for (int jj = 0; jj < 8; jj += 4) {
            const int c = n0 + tx*8 + jj;
            const int h = c >> 6, d = c & 63;
            float4 o;
            o.x = acc[i][jj+0] + bias[c+0];
            o.y = acc[i][jj+1] + bias[c+1];
            o.z = acc[i][jj+2] + bias[c+2];
            o.w = acc[i][jj+3] + bias[c+3];
            *(float4*)&dst[(((b*NH + h)*SEQ) + n)*HD + d] = o;
        }
    }
}

// Output projection: reads g_ctx [8192,768], writes d_out [8192,768]
__global__ __launch_bounds__(256) void out_gemm_kernel(
    const float* __restrict__ Wo, const float* __restrict__ bo,
    float* __restrict__ out)
{
    const int m0 = blockIdx.y * BM;
    const int n0 = blockIdx.x * BN;

    float acc[8][8];
    #pragma unroll
    for (int i = 0; i < 8; i++)
        #pragma unroll
        for (int j = 0; j < 8; j++) acc[i][j] = 0.f;

    gemm_mainloop(g_ctx, Wo, m0, n0, acc);

    const int ty = threadIdx.x >> 4, tx = threadIdx.x & 15;
    #pragma unroll
    for (int i = 0; i < 8; i++) {
        const int m = m0 + ty*8 + i;
        #pragma unroll
        for (int jj = 0; jj < 8; jj += 4) {
            const int c = n0 + tx*8 + jj;
            float4 o;
            o.x = acc[i][jj+0] + bo[c+0];
            o.y = acc[i][jj+1] + bo[c+1];
            o.z = acc[i][jj+2] + bo[c+2];
            o.w = acc[i][jj+3] + bo[c+3];
            *(float4*)&out[m*EMBED + c] = o;
        }
    }
}

// ---------------------------------------------------------------------------
// Flash attention: one block per (b*h, 64-row query tile). BR=BC=64, D=64.
// 256 threads = 16x16; each thread owns a 4x4 microtile of S and of O.
// Q/K staged d-major (transposed, pitch 72) -> conflict-free float4 reads.
// ---------------------------------------------------------------------------
#define QP 72
#define ATT_SMEM ((2*64*QP + 2*64*64) * 4)   // 69632 bytes

__global__ __launch_bounds__(256) void attn_kernel()
{
    extern __shared__ float sm[];
    float* Qst = sm;                 // [64 d][72]  (col r)
    float* Kst = sm + 64*QP;         // [64 d][72]  (col c)
    float* Vs  = sm + 2*64*QP;       // [64 c][64 d]
    float* Ps  = Vs + 64*64;         // [64 r][64 c]

    const int tid = threadIdx.x;
    const int ty  = tid >> 4;        // row group
    const int tx  = tid & 15;        // col group
    const int bh  = blockIdx.y;      // 0..47
    const int q0  = blockIdx.x * 64;

    const size_t base = (size_t)bh * SEQ * HD;
    const float* Qg = g_q + base;
    const float* Kg = g_k + base;
    const float* Vg = g_v + base;

    const int lrow = tid >> 4;       // 0..15
    const int lq   = (tid & 15) * 4; // 0..60, d-quad

    // Load Q tile transposed: Qst[d][r]
    #pragma unroll
    for (int it = 0; it < 4; it++) {
        const int r = lrow + it*16;
        float4 v = *(const float4*)(Qg + (size_t)(q0 + r)*HD + lq);
        Qst[(lq+0)*QP + r] = v.x;
        Qst[(lq+1)*QP + r] = v.y;
        Qst[(lq+2)*QP + r] = v.z;
        Qst[(lq+3)*QP + r] = v.w;
    }

    float acc[4][4];
    float mrow[4], lsum[4];
    #pragma unroll
    for (int i = 0; i < 4; i++) {
        mrow[i] = -1e30f; lsum[i] = 0.f;
        #pragma unroll
        for (int j = 0; j < 4; j++) acc[i][j] = 0.f;
    }

    const float scale = 0.125f;      // 64^-0.5

    for (int kt = 0; kt < SEQ/64; kt++) {
        __syncthreads();             // prev PV done before overwriting K/V
        #pragma unroll
        for (int it = 0; it < 4; it++) {
            const int r = lrow + it*16;
            float4 kv = *(const float4*)(Kg + (size_t)(kt*64 + r)*HD + lq);
            Kst[(lq+0)*QP + r] = kv.x;
            Kst[(lq+1)*QP + r] = kv.y;
            Kst[(lq+2)*QP + r] = kv.z;
            Kst[(lq+3)*QP + r] = kv.w;
            float4 vv = *(const float4*)(Vg + (size_t)(kt*64 + r)*HD + lq);
            *(float4*)&Vs[r*64 + lq] = vv;
        }
        __syncthreads();

        // S = Q K^T (4x4 microtile per thread), inner product over d
        float s[4][4];
        #pragma unroll
        for (int i = 0; i < 4; i++)
            #pragma unroll
            for (int j = 0; j < 4; j++) s[i][j] = 0.f;

        #pragma unroll 16
        for (int d = 0; d < HD; d++) {
            float4 q = *(const float4*)&Qst[d*QP + ty*4];
            float4 k = *(const float4*)&Kst[d*QP + tx*4];
            s[0][0]+=q.x*k.x; s[0][1]+=q.x*k.y; s[0][2]+=q.x*k.z; s[0][3]+=q.x*k.w;
            s[1][0]+=q.y*k.x; s[1][1]+=q.y*k.y; s[1][2]+=q.y*k.z; s[1][3]+=q.y*k.w;
            s[2][0]+=q.z*k.x; s[2][1]+=q.z*k.y; s[2][2]+=q.z*k.z; s[2][3]+=q.z*k.w;
            s[3][0]+=q.w*k.x; s[3][1]+=q.w*k.y; s[3][2]+=q.w*k.z; s[3][3]+=q.w*k.w;
        }

        // Online softmax per row; row stats reduced over the 16 tx lanes.
        #pragma unroll
        for (int i = 0; i < 4; i++) {
            #pragma unroll
            for (int j = 0; j < 4; j++) s[i][j] *= scale;
            float mt = fmaxf(fmaxf(s[i][0], s[i][1]), fmaxf(s[i][2], s[i][3]));
            #pragma unroll
            for (int o = 8; o >= 1; o >>= 1)
                mt = fmaxf(mt, __shfl_xor_sync(0xffffffffu, mt, o, 32));
            const float mnew = fmaxf(mrow[i], mt);
            const float corr = __expf(mrow[i] - mnew);
            mrow[i] = mnew;
            float rs = 0.f;
            #pragma unroll
            for (int j = 0; j < 4; j++) {
                s[i][j] = __expf(s[i][j] - mnew);
                rs += s[i][j];
            }
            #pragma unroll
            for (int o = 8; o >= 1; o >>= 1)
                rs += __shfl_xor_sync(0xffffffffu, rs, o, 32);
            lsum[i] = lsum[i]*corr + rs;
            #pragma unroll
            for (int j = 0; j < 4; j++) acc[i][j] *= corr;
            *(float4*)&Ps[(ty*4+i)*64 + tx*4] =
                make_float4(s[i][0], s[i][1], s[i][2], s[i][3]);
        }
        __syncthreads();

        // O += P V  (thread owns rows ty*4..+3, d-cols tx*4..+3)
        #pragma unroll 8
        for (int c = 0; c < 64; c++) {
            float4 v = *(const float4*)&Vs[c*64 + tx*4];
            float p0 = Ps[(ty*4+0)*64 + c];
            float p1 = Ps[(ty*4+1)*64 + c];
            float p2 = Ps[(ty*4+2)*64 + c];
            float p3 = Ps[(ty*4+3)*64 + c];
            acc[0][0]+=p0*v.x; acc[0][1]+=p0*v.y; acc[0][2]+=p0*v.z; acc[0][3]+=p0*v.w;
            acc[1][0]+=p1*v.x; acc[1][1]+=p1*v.y; acc[1][2]+=p1*v.z; acc[1][3]+=p1*v.w;
            acc[2][0]+=p2*v.x; acc[2][1]+=p2*v.y; acc[2][2]+=p2*v.z; acc[2][3]+=p2*v.w;
            acc[3][0]+=p3*v.x; acc[3][1]+=p3*v.y; acc[3][2]+=p3*v.z; acc[3][3]+=p3*v.w;
        }
    }

    // Normalize and write context in [B,N,C] layout (c = h*64 + d)
    const int b = bh / NH, h = bh % NH;
    #pragma unroll
    for (int i = 0; i < 4; i++) {
        const float inv = 1.0f / lsum[i];
        const int n = q0 + ty*4 + i;
        float4 o = make_float4(acc[i][0]*inv, acc[i][1]*inv,
                               acc[i][2]*inv, acc[i][3]*inv);
        *(float4*)&g_ctx[((size_t)(b*SEQ + n))*EMBED + h*HD + tx*4] = o;
    }
}

// ---------------------------------------------------------------------------
extern "C" void kernel_launch(void* const* d_in, const int* in_sizes, int n_in,
                              void* d_out, int out_size)
{
    const float* x  = (const float*)d_in[0];
    const float* Wq = (const float*)d_in[1];
    const float* bq = (const float*)d_in[2];
    const float* Wk = (const float*)d_in[3];
    const float* bk = (const float*)d_in[4];
    const float* Wv = (const float*)d_in[5];
    const float* bv = (const float*)d_in[6];
    const float* Wo = (const float*)d_in[7];
    const float* bo = (const float*)d_in[8];
    float* out = (float*)d_out;

    cudaFuncSetAttribute(attn_kernel,
                         cudaFuncAttributeMaxDynamicSharedMemorySize, ATT_SMEM);

    dim3 gq(EMBED/BN, MROWS/BM, 3);
    qkv_gemm_kernel<<<gq, 256>>>(x, Wq, bq, Wk, bk, Wv, bv);

    dim3 ga(SEQ/64, BATCH*NH);
    attn_kernel<<<ga, 256, ATT_SMEM>>>();

    dim3 go(EMBED/BN, MROWS/BM);
    out_gemm_kernel<<<go, 256>>>(Wo, bo, out);
}

// round 6
// speedup vs baseline: 1.0654x; 1.0654x over previous
#include <cuda_runtime.h>
#include <math.h>

#define EMBED 768
#define NH    12
#define HD    64
#define BATCH 4
#define SEQ   2048
#define MROWS (BATCH*SEQ)   // 8192

// Scratch (no allocations allowed): head-split Q/K/V and attention context.
__device__ float g_q[BATCH*NH*SEQ*HD];
__device__ float g_k[BATCH*NH*SEQ*HD];
__device__ float g_v[BATCH*NH*SEQ*HD];
__device__ float g_ctx[MROWS*EMBED];

// ---------------- f32x2 packed-FMA helpers (Blackwell FFMA2) ----------------
typedef unsigned long long ull;

__device__ __forceinline__ void fma2(ull &d, ull a, ull b) {
    asm("fma.rn.f32x2 %0, %1, %2, %0;" : "+l"(d) : "l"(a), "l"(b));
}
__device__ __forceinline__ ull mul2(ull a, ull b) {
    ull d;
    asm("mul.rn.f32x2 %0, %1, %2;" : "=l"(d) : "l"(a), "l"(b));
    return d;
}
__device__ __forceinline__ ull pack2(float lo, float hi) {
    ull r;
    asm("mov.b64 %0, {%1, %2};" : "=l"(r) : "f"(lo), "f"(hi));
    return r;
}
__device__ __forceinline__ float2 unpack2(ull v) {
    float lo, hi;
    asm("mov.b64 {%0, %1}, %2;" : "=f"(lo), "=f"(hi) : "l"(v));
    return make_float2(lo, hi);
}
union F4U { float4 f; ull u[2]; };

// ---------------------------------------------------------------------------
// GEMM: C[m,c] = sum_k A[m,k] * W[c,k]  (+bias)  -- "NT" layout, K=768
// 128x128 block tile, BK=16, 256 threads. FFMA2 paired along output-N.
// A duplicated (a,a) in smem so broadcast pairs are single LDS.64.
// Thread owns rows {ty*4..+3, 64+ty*4..+3} x cols {tx*4..+3, 64+tx*4..+3}.
// ---------------------------------------------------------------------------
#define BM 128
#define BN 128
#define BK 16

__device__ __forceinline__ void gemm_mainloop(const float* __restrict__ A,
                                              const float* __restrict__ W,
                                              int m0, int n0, ull acc[8][4])
{
    __shared__ float As2[BK][2*BM];   // duplicated: [k][2m]=[k][2m+1]=A[m,k]
    __shared__ float Bs[BK][BN];

    const int tid = threadIdx.x;
    const int lr  = tid >> 1;          // 0..127 (tile row for loads)
    const int lc  = (tid & 1) << 3;    // 0 or 8 (k offset for loads)
    const int ty  = tid >> 4;          // 0..15
    const int tx  = tid & 15;          // 0..15

    const float* Aptr = A + (size_t)(m0 + lr) * EMBED + lc;
    const float* Wptr = W + (size_t)(n0 + lr) * EMBED + lc;

    float4 a0 = *(const float4*)(Aptr + 0);
    float4 a1 = *(const float4*)(Aptr + 4);
    float4 b0 = *(const float4*)(Wptr + 0);
    float4 b1 = *(const float4*)(Wptr + 4);

    #pragma unroll 1
    for (int k0 = 0; k0 < EMBED; k0 += BK) {
        __syncthreads();
        *(float2*)&As2[lc+0][2*lr] = make_float2(a0.x, a0.x);
        *(float2*)&As2[lc+1][2*lr] = make_float2(a0.y, a0.y);
        *(float2*)&As2[lc+2][2*lr] = make_float2(a0.z, a0.z);
        *(float2*)&As2[lc+3][2*lr] = make_float2(a0.w, a0.w);
        *(float2*)&As2[lc+4][2*lr] = make_float2(a1.x, a1.x);
        *(float2*)&As2[lc+5][2*lr] = make_float2(a1.y, a1.y);
        *(float2*)&As2[lc+6][2*lr] = make_float2(a1.z, a1.z);
        *(float2*)&As2[lc+7][2*lr] = make_float2(a1.w, a1.w);
        Bs[lc+0][lr]=b0.x; Bs[lc+1][lr]=b0.y; Bs[lc+2][lr]=b0.z; Bs[lc+3][lr]=b0.w;
        Bs[lc+4][lr]=b1.x; Bs[lc+5][lr]=b1.y; Bs[lc+6][lr]=b1.z; Bs[lc+7][lr]=b1.w;
        __syncthreads();

        if (k0 + BK < EMBED) {        // prefetch next slab into registers
            a0 = *(const float4*)(Aptr + k0 + BK + 0);
            a1 = *(const float4*)(Aptr + k0 + BK + 4);
            b0 = *(const float4*)(Wptr + k0 + BK + 0);
            b1 = *(const float4*)(Wptr + k0 + BK + 4);
        }

        #pragma unroll
        for (int k = 0; k < BK; k++) {
            // a pairs (duplicated broadcast): rows ty*4.. and 64+ty*4..
            // row m lives at column 2m: rows 64+ty*4.. -> column 128+ty*8
            F4U a01, a23, a45, a67;
            a01.f = *(const float4*)&As2[k][ty*8 + 0];      // rows ty*4+0,1
            a23.f = *(const float4*)&As2[k][ty*8 + 4];      // rows ty*4+2,3
            a45.f = *(const float4*)&As2[k][128 + ty*8 + 0];// rows 64+ty*4+0,1
            a67.f = *(const float4*)&As2[k][128 + ty*8 + 4];// rows 64+ty*4+2,3
            // b pairs (natural): cols tx*4.. and 64+tx*4..
            F4U bA, bB;
            bA.f = *(const float4*)&Bs[k][tx*4];            // cols tx*4..+3
            bB.f = *(const float4*)&Bs[k][64 + tx*4];       // cols 64+tx*4..+3
            ull av[8] = { a01.u[0], a01.u[1], a23.u[0], a23.u[1],
                          a45.u[0], a45.u[1], a67.u[0], a67.u[1] };
            #pragma unroll
            for (int i = 0; i < 8; i++) {
                fma2(acc[i][0], av[i], bA.u[0]);
                fma2(acc[i][1], av[i], bA.u[1]);
                fma2(acc[i][2], av[i], bB.u[0]);
                fma2(acc[i][3], av[i], bB.u[1]);
            }
        }
    }
}

// QKV projections: grid.z in {0,1,2} selects Q/K/V; writes head-split layout
__global__ __launch_bounds__(256) void qkv_gemm_kernel(
    const float* __restrict__ x,
    const float* __restrict__ Wq, const float* __restrict__ bq,
    const float* __restrict__ Wk, const float* __restrict__ bk,
    const float* __restrict__ Wv, const float* __restrict__ bv)
{
    const float* W; const float* bias; float* dst;
    if (blockIdx.z == 0)      { W = Wq; bias = bq; dst = g_q; }
    else if (blockIdx.z == 1) { W = Wk; bias = bk; dst = g_k; }
    else                      { W = Wv; bias = bv; dst = g_v; }

    const int m0 = blockIdx.y * BM;
    const int n0 = blockIdx.x * BN;

    ull acc[8][4];
    #pragma unroll
    for (int i = 0; i < 8; i++)
        #pragma unroll
        for (int j = 0; j < 4; j++) acc[i][j] = 0ull;

    gemm_mainloop(x, W, m0, n0, acc);

    const int ty = threadIdx.x >> 4, tx = threadIdx.x & 15;
    #pragma unroll
    for (int i = 0; i < 8; i++) {
        const int m = m0 + ((i < 4) ? (ty*4 + i) : (64 + ty*4 + i - 4));
        const int b = m >> 11;          // /2048
        const int n = m & 2047;
        #pragma unroll
        for (int g = 0; g < 2; g++) {
            const int c = n0 + g*64 + tx*4;
            const int h = c >> 6, d = c & 63;
            float2 p0 = unpack2(acc[i][g*2 + 0]);
            float2 p1 = unpack2(acc[i][g*2 + 1]);
            float4 o;
            o.x = p0.x + bias[c+0];
            o.y = p0.y + bias[c+1];
            o.z = p1.x + bias[c+2];
            o.w = p1.y + bias[c+3];
            *(float4*)&dst[(((size_t)(b*NH + h)*SEQ) + n)*HD + d] = o;
        }
    }
}

// Output projection: reads g_ctx [8192,768], writes d_out [8192,768]
__global__ __launch_bounds__(256) void out_gemm_kernel(
    const float* __restrict__ Wo, const float* __restrict__ bo,
    float* __restrict__ out)
{
    const int m0 = blockIdx.y * BM;
    const int n0 = blockIdx.x * BN;

    ull acc[8][4];
    #pragma unroll
    for (int i = 0; i < 8; i++)
        #pragma unroll
        for (int j = 0; j < 4; j++) acc[i][j] = 0ull;

    gemm_mainloop(g_ctx, Wo, m0, n0, acc);

    const int ty = threadIdx.x >> 4, tx = threadIdx.x & 15;
    #pragma unroll
    for (int i = 0; i < 8; i++) {
        const int m = m0 + ((i < 4) ? (ty*4 + i) : (64 + ty*4 + i - 4));
        #pragma unroll
        for (int g = 0; g < 2; g++) {
            const int c = n0 + g*64 + tx*4;
            float2 p0 = unpack2(acc[i][g*2 + 0]);
            float2 p1 = unpack2(acc[i][g*2 + 1]);
            float4 o;
            o.x = p0.x + bo[c+0];
            o.y = p0.y + bo[c+1];
            o.z = p1.x + bo[c+2];
            o.w = p1.y + bo[c+3];
            *(float4*)&out[(size_t)m*EMBED + c] = o;
        }
    }
}

// ---------------------------------------------------------------------------
// Flash attention with FFMA2. BR=BC=64, D=64. 256 threads = 16x16.
// S = QK^T paired along d (natural 64-bit pairs from row-major Q/K; K quad-
// swizzled for bank-conflict-free lane reads). PV paired along d (natural
// pairs from V); P stored duplicated (p,p) so broadcast pairs are LDS.64.
// ---------------------------------------------------------------------------
// smem: Qs 64x64 f32 (16KB) | Ks 64x64 f32 swizzled (16KB)
//       Vs 64x64 f32 (16KB) | Ps2 64x64 ull duplicated (32KB)  => 80KB
#define ATT_SMEM ((3*64*64 + 64*64*2) * 4)   // 81920 bytes

__global__ __launch_bounds__(256) void attn_kernel()
{
    extern __shared__ float sm[];
    float* Qs  = sm;                       // [64 r][64 d]
    float* Ks  = sm + 64*64;               // [64 c][64 d] quad-swizzled
    float* Vs  = sm + 2*64*64;             // [64 c][64 d]
    ull*   Ps2 = (ull*)(sm + 3*64*64);     // [64 r][64 c] duplicated pairs

    const int tid = threadIdx.x;
    const int ty  = tid >> 4;        // row group 0..15
    const int tx  = tid & 15;        // col group 0..15
    const int bh  = blockIdx.y;      // 0..47
    const int q0  = blockIdx.x * 64;

    const size_t base = (size_t)bh * SEQ * HD;
    const float* Qg = g_q + base;
    const float* Kg = g_k + base;
    const float* Vg = g_v + base;

    const int lrow = tid >> 4;       // 0..15
    const int lq   = (tid & 15) * 4; // 0..60, d-quad (quad index = tx)
    const float scale = 0.125f;      // 64^-0.5 (folded into Q)

    // Load Q tile row-major, pre-scaled
    #pragma unroll
    for (int it = 0; it < 4; it++) {
        const int r = lrow + it*16;
        float4 v = *(const float4*)(Qg + (size_t)(q0 + r)*HD + lq);
        v.x *= scale; v.y *= scale; v.z *= scale; v.w *= scale;
        *(float4*)&Qs[r*64 + lq] = v;
    }

    ull acc2[4][2];                  // rows i x d-pairs {(d0,d1),(d2,d3)}
    float mrow[4], lsum[4];
    #pragma unroll
    for (int i = 0; i < 4; i++) {
        mrow[i] = -1e30f; lsum[i] = 0.f;
        acc2[i][0] = 0ull; acc2[i][1] = 0ull;
    }

    for (int kt = 0; kt < SEQ/64; kt++) {
        __syncthreads();             // prev PV done before overwriting K/V
        #pragma unroll
        for (int it = 0; it < 4; it++) {
            const int r = lrow + it*16;
            float4 kv = *(const float4*)(Kg + (size_t)(kt*64 + r)*HD + lq);
            const int key = (r >> 2) & 7;
            *(float4*)&Ks[r*64 + ((tx ^ key) << 2)] = kv;   // quad-swizzled
            float4 vv = *(const float4*)(Vg + (size_t)(kt*64 + r)*HD + lq);
            *(float4*)&Vs[r*64 + lq] = vv;
        }
        __syncthreads();

        // S = Q K^T, paired along d: s2 holds (even-d, odd-d) partials
        ull s2[4][4];
        #pragma unroll
        for (int i = 0; i < 4; i++)
            #pragma unroll
            for (int j = 0; j < 4; j++) s2[i][j] = 0ull;

        const int kkey = tx & 7;     // == ((tx*4+j)>>2)&7 for j<4
        #pragma unroll 8
        for (int qd = 0; qd < 16; qd++) {
            F4U qv[4], kv[4];
            #pragma unroll
            for (int i = 0; i < 4; i++)
                qv[i].f = *(const float4*)&Qs[(ty*4+i)*64 + (qd << 2)];
            #pragma unroll
            for (int j = 0; j < 4; j++)
                kv[j].f = *(const float4*)&Ks[(tx*4+j)*64 + ((qd ^ kkey) << 2)];
            #pragma unroll
            for (int p = 0; p < 2; p++)
                #pragma unroll
                for (int i = 0; i < 4; i++)
                    #pragma unroll
                    for (int j = 0; j < 4; j++)
                        fma2(s2[i][j], qv[i].u[p], kv[j].u[p]);
        }

        // Reduce pairs, online softmax per row (stats over 16 tx lanes)
        #pragma unroll
        for (int i = 0; i < 4; i++) {
            float s[4];
            #pragma unroll
            for (int j = 0; j < 4; j++) {
                float2 t = unpack2(s2[i][j]);
                s[j] = t.x + t.y;
            }
            float mt = fmaxf(fmaxf(s[0], s[1]), fmaxf(s[2], s[3]));
            #pragma unroll
            for (int o = 8; o >= 1; o >>= 1)
                mt = fmaxf(mt, __shfl_xor_sync(0xffffffffu, mt, o, 32));
            const float mnew = fmaxf(mrow[i], mt);
            const float corr = __expf(mrow[i] - mnew);
            mrow[i] = mnew;
            float rs = 0.f;
            #pragma unroll
            for (int j = 0; j < 4; j++) {
                s[j] = __expf(s[j] - mnew);
                rs += s[j];
            }
            #pragma unroll
            for (int o = 8; o >= 1; o >>= 1)
                rs += __shfl_xor_sync(0xffffffffu, rs, o, 32);
            lsum[i] = lsum[i]*corr + rs;
            const ull cc = pack2(corr, corr);
            acc2[i][0] = mul2(acc2[i][0], cc);
            acc2[i][1] = mul2(acc2[i][1], cc);
            // duplicated P write: (p,p) pairs
            F4U w0, w1;
            w0.f = make_float4(s[0], s[0], s[1], s[1]);
            w1.f = make_float4(s[2], s[2], s[3], s[3]);
            *(float4*)&Ps2[(ty*4+i)*64 + tx*4 + 0] = w0.f;
            *(float4*)&Ps2[(ty*4+i)*64 + tx*4 + 2] = w1.f;
        }
        __syncthreads();

        // O += P V, paired along d (thread owns d-cols tx*4..+3)
        #pragma unroll 8
        for (int c = 0; c < 64; c++) {
            F4U v; v.f = *(const float4*)&Vs[c*64 + tx*4];
            ull p0 = Ps2[(ty*4+0)*64 + c];
            ull p1 = Ps2[(ty*4+1)*64 + c];
            ull p2 = Ps2[(ty*4+2)*64 + c];
            ull p3 = Ps2[(ty*4+3)*64 + c];
            fma2(acc2[0][0], p0, v.u[0]); fma2(acc2[0][1], p0, v.u[1]);
            fma2(acc2[1][0], p1, v.u[0]); fma2(acc2[1][1], p1, v.u[1]);
            fma2(acc2[2][0], p2, v.u[0]); fma2(acc2[2][1], p2, v.u[1]);
            fma2(acc2[3][0], p3, v.u[0]); fma2(acc2[3][1], p3, v.u[1]);
        }
    }

    // Normalize and write context in [B,N,C] layout (c = h*64 + d)
    const int b = bh / NH, h = bh % NH;
    #pragma unroll
    for (int i = 0; i < 4; i++) {
        const float inv = 1.0f / lsum[i];
        const int n = q0 + ty*4 + i;
        float2 d01 = unpack2(acc2[i][0]);
        float2 d23 = unpack2(acc2[i][1]);
        float4 o = make_float4(d01.x*inv, d01.y*inv, d23.x*inv, d23.y*inv);
        *(float4*)&g_ctx[((size_t)(b*SEQ + n))*EMBED + h*HD + tx*4] = o;
    }
}

// ---------------------------------------------------------------------------
extern "C" void kernel_launch(void* const* d_in, const int* in_sizes, int n_in,
                              void* d_out, int out_size)
{
    const float* x  = (const float*)d_in[0];
    const float* Wq = (const float*)d_in[1];
    const float* bq = (const float*)d_in[2];
    const float* Wk = (const float*)d_in[3];
    const float* bk = (const float*)d_in[4];
    const float* Wv = (const float*)d_in[5];
    const float* bv = (const float*)d_in[6];
    const float* Wo = (const float*)d_in[7];
    const float* bo = (const float*)d_in[8];
    float* out = (float*)d_out;

    cudaFuncSetAttribute(attn_kernel,
                         cudaFuncAttributeMaxDynamicSharedMemorySize, ATT_SMEM);

    dim3 gq(EMBED/BN, MROWS/BM, 3);
    qkv_gemm_kernel<<<gq, 256>>>(x, Wq, bq, Wk, bk, Wv, bv);

    dim3 ga(SEQ/64, BATCH*NH);
    attn_kernel<<<ga, 256, ATT_SMEM>>>();

    dim3 go(EMBED/BN, MROWS/BM);
    out_gemm_kernel<<<go, 256>>>(Wo, bo, out);
}

// round 9
// speedup vs baseline: 1.3829x; 1.2981x over previous
#include <cuda_runtime.h>
#include <math.h>
#include <stdint.h>

#define EMBED 768
#define NH    12
#define HD    64
#define BATCH 4
#define SEQ   2048
#define MROWS (BATCH*SEQ)   // 8192

// Scratch (no allocations allowed): head-split Q/K/V and attention context.
__device__ float g_q[BATCH*NH*SEQ*HD];
__device__ float g_k[BATCH*NH*SEQ*HD];
__device__ float g_v[BATCH*NH*SEQ*HD];
__device__ float g_ctx[MROWS*EMBED];

// ---------------- f32x2 packed-FMA helpers (Blackwell FFMA2) ----------------
typedef unsigned long long ull;

__device__ __forceinline__ void fma2(ull &d, ull a, ull b) {
    asm("fma.rn.f32x2 %0, %1, %2, %0;" : "+l"(d) : "l"(a), "l"(b));
}
__device__ __forceinline__ ull mul2(ull a, ull b) {
    ull d;
    asm("mul.rn.f32x2 %0, %1, %2;" : "=l"(d) : "l"(a), "l"(b));
    return d;
}
__device__ __forceinline__ ull pack2(float lo, float hi) {
    ull r;
    asm("mov.b64 %0, {%1, %2};" : "=l"(r) : "f"(lo), "f"(hi));
    return r;
}
__device__ __forceinline__ float2 unpack2(ull v) {
    float lo, hi;
    asm("mov.b64 {%0, %1}, %2;" : "=f"(lo), "=f"(hi) : "l"(v));
    return make_float2(lo, hi);
}
union F4U { float4 f; ull u[2]; };

// ---------------- mma.sync bf16 helpers (legacy tensor path) ----------------
// Split fp32 pair (x=lower, y=upper) into bf16x2 hi + bf16x2 lo (compensated).
__device__ __forceinline__ void bf16_split2(float x, float y,
                                            uint32_t &h2, uint32_t &l2) {
    asm("cvt.rn.bf16x2.f32 %0, %1, %2;" : "=r"(h2) : "f"(y), "f"(x));
    float hx = __uint_as_float(h2 << 16);
    float hy = __uint_as_float(h2 & 0xFFFF0000u);
    asm("cvt.rn.bf16x2.f32 %0, %1, %2;" : "=r"(l2) : "f"(y - hy), "f"(x - hx));
}
__device__ __forceinline__ void mma_bf16(float (&c)[4],
                                         uint32_t a0, uint32_t a1,
                                         uint32_t a2, uint32_t a3,
                                         uint32_t b0, uint32_t b1) {
    asm("mma.sync.aligned.m16n8k16.row.col.f32.bf16.bf16.f32 "
        "{%0,%1,%2,%3}, {%4,%5,%6,%7}, {%8,%9}, {%0,%1,%2,%3};"
        : "+f"(c[0]), "+f"(c[1]), "+f"(c[2]), "+f"(c[3])
        : "r"(a0), "r"(a1), "r"(a2), "r"(a3), "r"(b0), "r"(b1));
}

// ---------------------------------------------------------------------------
// Tensor-core GEMM: C[m,c] = sum_k A[m,k]*W[c,k] (+bias). NT layout, K=768.
// CTA 128x128, 8 warps (2x4) of 64x32, K-slab 32 (2 k16-steps).
// bf16 2-term compensation: 3 mma per tile-step (ah*bh, al*bh, ah*bl).
// SMEM holds pre-split operands in fragment-permuted layout:
//   A tile (16m x 16k) = 32 lanes x 16B (one LDS.128 per frag)
//   B tile ( 8n x 16k) = 32 lanes x  8B (one LDS.64  per frag)
// Store-side swizzles (idx^=ks; slot^=(slot>>3)&1; B slot^=(ks<<3)) make the
// producer STS.32 scatter conflict-free; loads stay conflict-free.
// ---------------------------------------------------------------------------
#define NSLAB (EMBED/32)   // 24

__device__ __forceinline__ void mma_gemm_mainloop(
    const float* __restrict__ A, const float* __restrict__ W,
    int m0, int n0, float C[4][4][4])
{
    __shared__ uint32_t AH[2048], AL[2048], BH[2048], BL[2048];  // 8KB each

    const int tid  = threadIdx.x;
    const int lane = tid & 31;
    const int wid  = tid >> 5;
    const int wr   = wid >> 2;       // warp row 0..1 (64 m-rows each)
    const int wc   = wid & 3;        // warp col 0..3 (32 n-cols each)

    // Producer prefetch (slab 0)
    float4 pa[4], pw[4];
    #pragma unroll
    for (int i = 0; i < 4; i++) {
        const int f = i * 256 + tid;
        const int row = f >> 3, k4 = (f & 7) * 4;
        pa[i] = *(const float4*)(A + (size_t)(m0 + row) * EMBED + k4);
        pw[i] = *(const float4*)(W + (size_t)(n0 + row) * EMBED + k4);
    }

    #pragma unroll 1
    for (int s = 0; s < NSLAB; s++) {
        __syncthreads();   // prev slab's mma done before overwrite

        // Split + permuted STS (conflict-free)
        #pragma unroll
        for (int i = 0; i < 4; i++) {
            const int f   = i * 256 + tid;
            const int row = f >> 3;
            const int k4  = (f & 7) * 4;
            const int ks  = k4 >> 4;
            const int kk  = k4 & 15;
            const int hk  = kk >> 3;
            const int t0  = (kk & 7) >> 1;   // 0 or 2
            uint32_t h2, l2;
            // A element pairs (row, k4..k4+3)
            {
                const int g = row & 7, hm = (row >> 3) & 1, mt = row >> 4;
                const int idx  = (hm + 2 * hk) ^ ks;
                const int base = (ks * 8 + mt) * 128 + idx;
                bf16_split2(pa[i].x, pa[i].y, h2, l2);
                int sl = g * 4 + t0;  int sp = sl ^ ((sl >> 3) & 1);
                AH[base + sp * 4] = h2;  AL[base + sp * 4] = l2;
                bf16_split2(pa[i].z, pa[i].w, h2, l2);
                sl = g * 4 + t0 + 1;  sp = sl ^ ((sl >> 3) & 1);
                AH[base + sp * 4] = h2;  AL[base + sp * 4] = l2;
            }
            // B element pairs (row=n, k4..k4+3)
            {
                const int gn = row & 7, nt = row >> 3;
                const int base = (ks * 16 + nt) * 64 + hk;
                bf16_split2(pw[i].x, pw[i].y, h2, l2);
                int sl = gn * 4 + t0;
                int sp = (sl ^ ((sl >> 3) & 1)) ^ (ks << 3);
                BH[base + sp * 2] = h2;  BL[base + sp * 2] = l2;
                bf16_split2(pw[i].z, pw[i].w, h2, l2);
                sl = gn * 4 + t0 + 1;
                sp = (sl ^ ((sl >> 3) & 1)) ^ (ks << 3);
                BH[base + sp * 2] = h2;  BL[base + sp * 2] = l2;
            }
        }
        __syncthreads();

        // Prefetch next slab while mma runs
        if (s + 1 < NSLAB) {
            const int k0 = (s + 1) * 32;
            #pragma unroll
            for (int i = 0; i < 4; i++) {
                const int f = i * 256 + tid;
                const int row = f >> 3, k4 = (f & 7) * 4;
                pa[i] = *(const float4*)(A + (size_t)(m0 + row) * EMBED + k0 + k4);
                pw[i] = *(const float4*)(W + (size_t)(n0 + row) * EMBED + k0 + k4);
            }
        }

        // MMA over the slab (2 k16-steps)
        const int lp = lane ^ ((lane >> 3) & 1);
        #pragma unroll
        for (int ks = 0; ks < 2; ks++) {
            uint4 ah[4], al4[4];
            uint2 bh[4], bl4[4];
            #pragma unroll
            for (int mt = 0; mt < 4; mt++) {
                const int off = (ks * 8 + wr * 4 + mt) * 128 + lp * 4;
                ah[mt]  = *(const uint4*)&AH[off];
                al4[mt] = *(const uint4*)&AL[off];
            }
            const int lpb = lp ^ (ks << 3);
            #pragma unroll
            for (int nt = 0; nt < 4; nt++) {
                const int off = (ks * 16 + wc * 4 + nt) * 64 + lpb * 2;
                bh[nt]  = *(const uint2*)&BH[off];
                bl4[nt] = *(const uint2*)&BL[off];
            }
            #pragma unroll
            for (int mt = 0; mt < 4; mt++) {
                // idx was XOR'd with ks: for ks=1 the regs come back swapped
                const uint32_t a0 = ks ? ah[mt].y  : ah[mt].x;
                const uint32_t a1 = ks ? ah[mt].x  : ah[mt].y;
                const uint32_t a2 = ks ? ah[mt].w  : ah[mt].z;
                const uint32_t a3 = ks ? ah[mt].z  : ah[mt].w;
                const uint32_t e0 = ks ? al4[mt].y : al4[mt].x;
                const uint32_t e1 = ks ? al4[mt].x : al4[mt].y;
                const uint32_t e2 = ks ? al4[mt].w : al4[mt].z;
                const uint32_t e3 = ks ? al4[mt].z : al4[mt].w;
                #pragma unroll
                for (int nt = 0; nt < 4; nt++) {
                    mma_bf16(C[mt][nt], a0, a1, a2, a3, bh[nt].x, bh[nt].y);
                    mma_bf16(C[mt][nt], e0, e1, e2, e3, bh[nt].x, bh[nt].y);
                    mma_bf16(C[mt][nt], a0, a1, a2, a3, bl4[nt].x, bl4[nt].y);
                }
            }
        }
    }
}

// QKV projections: grid.z selects Q/K/V; writes head-split layout
__global__ __launch_bounds__(256) void qkv_mma_kernel(
    const float* __restrict__ x,
    const float* __restrict__ Wq, const float* __restrict__ bq,
    const float* __restrict__ Wk, const float* __restrict__ bk,
    const float* __restrict__ Wv, const float* __restrict__ bv)
{
    const float* W; const float* bias; float* dst;
    if (blockIdx.z == 0)      { W = Wq; bias = bq; dst = g_q; }
    else if (blockIdx.z == 1) { W = Wk; bias = bk; dst = g_k; }
    else                      { W = Wv; bias = bv; dst = g_v; }

    const int m0 = blockIdx.y * 128;
    const int n0 = blockIdx.x * 128;

    float C[4][4][4];
    #pragma unroll
    for (int mt = 0; mt < 4; mt++)
        #pragma unroll
        for (int nt = 0; nt < 4; nt++)
            #pragma unroll
            for (int q = 0; q < 4; q++) C[mt][nt][q] = 0.f;

    mma_gemm_mainloop(x, W, m0, n0, C);

    const int lane = threadIdx.x & 31;
    const int wid  = threadIdx.x >> 5;
    const int wr = wid >> 2, wc = wid & 3;
    const int g = lane >> 2, t = lane & 3;
    #pragma unroll
    for (int mt = 0; mt < 4; mt++) {
        #pragma unroll
        for (int nt = 0; nt < 4; nt++) {
            const int col = wc * 32 + nt * 8 + t * 2;
            const int c = n0 + col;
            const int h = c >> 6, d = c & 63;
            const float2 bv2 = *(const float2*)(bias + c);
            #pragma unroll
            for (int half = 0; half < 2; half++) {
                const int m = m0 + wr * 64 + mt * 16 + g + half * 8;
                const int b = m >> 11;
                const int n = m & 2047;
                float2 o;
                o.x = C[mt][nt][half * 2 + 0] + bv2.x;
                o.y = C[mt][nt][half * 2 + 1] + bv2.y;
                *(float2*)&dst[(((size_t)(b * NH + h) * SEQ) + n) * HD + d] = o;
            }
        }
    }
}

// Output projection: reads g_ctx, writes d_out row-major [8192,768]
__global__ __launch_bounds__(256) void out_mma_kernel(
    const float* __restrict__ Wo, const float* __restrict__ bo,
    float* __restrict__ out)
{
    const int m0 = blockIdx.y * 128;
    const int n0 = blockIdx.x * 128;

    float C[4][4][4];
    #pragma unroll
    for (int mt = 0; mt < 4; mt++)
        #pragma unroll
        for (int nt = 0; nt < 4; nt++)
            #pragma unroll
            for (int q = 0; q < 4; q++) C[mt][nt][q] = 0.f;

    mma_gemm_mainloop(g_ctx, Wo, m0, n0, C);

    const int lane = threadIdx.x & 31;
    const int wid  = threadIdx.x >> 5;
    const int wr = wid >> 2, wc = wid & 3;
    const int g = lane >> 2, t = lane & 3;
    #pragma unroll
    for (int mt = 0; mt < 4; mt++) {
        #pragma unroll
        for (int nt = 0; nt < 4; nt++) {
            const int c = n0 + wc * 32 + nt * 8 + t * 2;
            const float2 bv2 = *(const float2*)(bo + c);
            #pragma unroll
            for (int half = 0; half < 2; half++) {
                const int m = m0 + wr * 64 + mt * 16 + g + half * 8;
                float2 o;
                o.x = C[mt][nt][half * 2 + 0] + bv2.x;
                o.y = C[mt][nt][half * 2 + 1] + bv2.y;
                *(float2*)&out[(size_t)m * EMBED + c] = o;
            }
        }
    }
}

// ---------------------------------------------------------------------------
// Flash attention with FFMA2 (unchanged passing version).
// ---------------------------------------------------------------------------
#define ATT_SMEM ((3*64*64 + 64*64*2) * 4)   // 81920 bytes

__global__ __launch_bounds__(256) void attn_kernel()
{
    extern __shared__ float sm[];
    float* Qs  = sm;                       // [64 r][64 d]
    float* Ks  = sm + 64*64;               // [64 c][64 d] quad-swizzled
    float* Vs  = sm + 2*64*64;             // [64 c][64 d]
    ull*   Ps2 = (ull*)(sm + 3*64*64);     // [64 r][64 c] duplicated pairs

    const int tid = threadIdx.x;
    const int ty  = tid >> 4;
    const int tx  = tid & 15;
    const int bh  = blockIdx.y;
    const int q0  = blockIdx.x * 64;

    const size_t base = (size_t)bh * SEQ * HD;
    const float* Qg = g_q + base;
    const float* Kg = g_k + base;
    const float* Vg = g_v + base;

    const int lrow = tid >> 4;
    const int lq   = (tid & 15) * 4;
    const float scale = 0.125f;

    #pragma unroll
    for (int it = 0; it < 4; it++) {
        const int r = lrow + it*16;
        float4 v = *(const float4*)(Qg + (size_t)(q0 + r)*HD + lq);
        v.x *= scale; v.y *= scale; v.z *= scale; v.w *= scale;
        *(float4*)&Qs[r*64 + lq] = v;
    }

    ull acc2[4][2];
    float mrow[4], lsum[4];
    #pragma unroll
    for (int i = 0; i < 4; i++) {
        mrow[i] = -1e30f; lsum[i] = 0.f;
        acc2[i][0] = 0ull; acc2[i][1] = 0ull;
    }

    for (int kt = 0; kt < SEQ/64; kt++) {
        __syncthreads();
        #pragma unroll
        for (int it = 0; it < 4; it++) {
            const int r = lrow + it*16;
            float4 kv = *(const float4*)(Kg + (size_t)(kt*64 + r)*HD + lq);
            const int key = (r >> 2) & 7;
            *(float4*)&Ks[r*64 + ((tx ^ key) << 2)] = kv;
            float4 vv = *(const float4*)(Vg + (size_t)(kt*64 + r)*HD + lq);
            *(float4*)&Vs[r*64 + lq] = vv;
        }
        __syncthreads();

        ull s2[4][4];
        #pragma unroll
        for (int i = 0; i < 4; i++)
            #pragma unroll
            for (int j = 0; j < 4; j++) s2[i][j] = 0ull;

        const int kkey = tx & 7;
        #pragma unroll 8
        for (int qd = 0; qd < 16; qd++) {
            F4U qv[4], kv[4];
            #pragma unroll
            for (int i = 0; i < 4; i++)
                qv[i].f = *(const float4*)&Qs[(ty*4+i)*64 + (qd << 2)];
            #pragma unroll
            for (int j = 0; j < 4; j++)
                kv[j].f = *(const float4*)&Ks[(tx*4+j)*64 + ((qd ^ kkey) << 2)];
            #pragma unroll
            for (int p = 0; p < 2; p++)
                #pragma unroll
                for (int i = 0; i < 4; i++)
                    #pragma unroll
                    for (int j = 0; j < 4; j++)
                        fma2(s2[i][j], qv[i].u[p], kv[j].u[p]);
        }

        #pragma unroll
        for (int i = 0; i < 4; i++) {
            float s[4];
            #pragma unroll
            for (int j = 0; j < 4; j++) {
                float2 t2 = unpack2(s2[i][j]);
                s[j] = t2.x + t2.y;
            }
            float mt = fmaxf(fmaxf(s[0], s[1]), fmaxf(s[2], s[3]));
            #pragma unroll
            for (int o = 8; o >= 1; o >>= 1)
                mt = fmaxf(mt, __shfl_xor_sync(0xffffffffu, mt, o, 32));
            const float mnew = fmaxf(mrow[i], mt);
            const float corr = __expf(mrow[i] - mnew);
            mrow[i] = mnew;
            float rs = 0.f;
            #pragma unroll
            for (int j = 0; j < 4; j++) {
                s[j] = __expf(s[j] - mnew);
                rs += s[j];
            }
            #pragma unroll
            for (int o = 8; o >= 1; o >>= 1)
                rs += __shfl_xor_sync(0xffffffffu, rs, o, 32);
            lsum[i] = lsum[i]*corr + rs;
            const ull cc = pack2(corr, corr);
            acc2[i][0] = mul2(acc2[i][0], cc);
            acc2[i][1] = mul2(acc2[i][1], cc);
            F4U w0, w1;
            w0.f = make_float4(s[0], s[0], s[1], s[1]);
            w1.f = make_float4(s[2], s[2], s[3], s[3]);
            *(float4*)&Ps2[(ty*4+i)*64 + tx*4 + 0] = w0.f;
            *(float4*)&Ps2[(ty*4+i)*64 + tx*4 + 2] = w1.f;
        }
        __syncthreads();

        #pragma unroll 8
        for (int c = 0; c < 64; c++) {
            F4U v; v.f = *(const float4*)&Vs[c*64 + tx*4];
            ull p0 = Ps2[(ty*4+0)*64 + c];
            ull p1 = Ps2[(ty*4+1)*64 + c];
            ull p2 = Ps2[(ty*4+2)*64 + c];
            ull p3 = Ps2[(ty*4+3)*64 + c];
            fma2(acc2[0][0], p0, v.u[0]); fma2(acc2[0][1], p0, v.u[1]);
            fma2(acc2[1][0], p1, v.u[0]); fma2(acc2[1][1], p1, v.u[1]);
            fma2(acc2[2][0], p2, v.u[0]); fma2(acc2[2][1], p2, v.u[1]);
            fma2(acc2[3][0], p3, v.u[0]); fma2(acc2[3][1], p3, v.u[1]);
        }
    }

    const int b = bh / NH, h = bh % NH;
    #pragma unroll
    for (int i = 0; i < 4; i++) {
        const float inv = 1.0f / lsum[i];
        const int n = q0 + ty*4 + i;
        float2 d01 = unpack2(acc2[i][0]);
        float2 d23 = unpack2(acc2[i][1]);
        float4 o = make_float4(d01.x*inv, d01.y*inv, d23.x*inv, d23.y*inv);
        *(float4*)&g_ctx[((size_t)(b*SEQ + n))*EMBED + h*HD + tx*4] = o;
    }
}

// ---------------------------------------------------------------------------
extern "C" void kernel_launch(void* const* d_in, const int* in_sizes, int n_in,
                              void* d_out, int out_size)
{
    const float* x  = (const float*)d_in[0];
    const float* Wq = (const float*)d_in[1];
    const float* bq = (const float*)d_in[2];
    const float* Wk = (const float*)d_in[3];
    const float* bk = (const float*)d_in[4];
    const float* Wv = (const float*)d_in[5];
    const float* bv = (const float*)d_in[6];
    const float* Wo = (const float*)d_in[7];
    const float* bo = (const float*)d_in[8];
    float* out = (float*)d_out;

    cudaFuncSetAttribute(attn_kernel,
                         cudaFuncAttributeMaxDynamicSharedMemorySize, ATT_SMEM);

    dim3 gq(EMBED/128, MROWS/128, 3);   // (6, 64, 3)
    qkv_mma_kernel<<<gq, 256>>>(x, Wq, bq, Wk, bk, Wv, bv);

    dim3 ga(SEQ/64, BATCH*NH);
    attn_kernel<<<ga, 256, ATT_SMEM>>>();

    dim3 go(EMBED/128, MROWS/128);      // (6, 64)
    out_mma_kernel<<<go, 256>>>(Wo, bo, out);
}

// round 10
// speedup vs baseline: 2.6630x; 1.9256x over previous
#include <cuda_runtime.h>
#include <math.h>
#include <stdint.h>

#define EMBED 768
#define NH    12
#define HD    64
#define BATCH 4
#define SEQ   2048
#define MROWS (BATCH*SEQ)   // 8192

// Scratch (no allocations allowed): head-split Q/K/V and attention context.
__device__ float g_q[BATCH*NH*SEQ*HD];
__device__ float g_k[BATCH*NH*SEQ*HD];
__device__ float g_v[BATCH*NH*SEQ*HD];
__device__ float g_ctx[MROWS*EMBED];

typedef unsigned long long ull;

// ---------------- mma.sync bf16 helpers (legacy tensor path) ----------------
// Split fp32 pair (x=lower, y=upper) into bf16x2 hi + bf16x2 lo (compensated).
__device__ __forceinline__ void bf16_split2(float x, float y,
                                            uint32_t &h2, uint32_t &l2) {
    asm("cvt.rn.bf16x2.f32 %0, %1, %2;" : "=r"(h2) : "f"(y), "f"(x));
    float hx = __uint_as_float(h2 << 16);
    float hy = __uint_as_float(h2 & 0xFFFF0000u);
    asm("cvt.rn.bf16x2.f32 %0, %1, %2;" : "=r"(l2) : "f"(y - hy), "f"(x - hx));
}
__device__ __forceinline__ void mma_bf16(float (&c)[4],
                                         uint32_t a0, uint32_t a1,
                                         uint32_t a2, uint32_t a3,
                                         uint32_t b0, uint32_t b1) {
    asm("mma.sync.aligned.m16n8k16.row.col.f32.bf16.bf16.f32 "
        "{%0,%1,%2,%3}, {%4,%5,%6,%7}, {%8,%9}, {%0,%1,%2,%3};"
        : "+f"(c[0]), "+f"(c[1]), "+f"(c[2]), "+f"(c[3])
        : "r"(a0), "r"(a1), "r"(a2), "r"(a3), "r"(b0), "r"(b1));
}
#define BAR_PAIR(id) \
    asm volatile("bar.sync %0, 64;" :: "r"(id) : "memory")

// ---------------------------------------------------------------------------
// Tensor-core GEMM (unchanged from passing R9): C = A*W^T + bias.
// ---------------------------------------------------------------------------
#define NSLAB (EMBED/32)   // 24

__device__ __forceinline__ void mma_gemm_mainloop(
    const float* __restrict__ A, const float* __restrict__ W,
    int m0, int n0, float C[4][4][4])
{
    __shared__ uint32_t AH[2048], AL[2048], BH[2048], BL[2048];  // 8KB each

    const int tid  = threadIdx.x;
    const int lane = tid & 31;
    const int wid  = tid >> 5;
    const int wr   = wid >> 2;
    const int wc   = wid & 3;

    float4 pa[4], pw[4];
    #pragma unroll
    for (int i = 0; i < 4; i++) {
        const int f = i * 256 + tid;
        const int row = f >> 3, k4 = (f & 7) * 4;
        pa[i] = *(const float4*)(A + (size_t)(m0 + row) * EMBED + k4);
        pw[i] = *(const float4*)(W + (size_t)(n0 + row) * EMBED + k4);
    }

    #pragma unroll 1
    for (int s = 0; s < NSLAB; s++) {
        __syncthreads();

        #pragma unroll
        for (int i = 0; i < 4; i++) {
            const int f   = i * 256 + tid;
            const int row = f >> 3;
            const int k4  = (f & 7) * 4;
            const int ks  = k4 >> 4;
            const int kk  = k4 & 15;
            const int hk  = kk >> 3;
            const int t0  = (kk & 7) >> 1;
            uint32_t h2, l2;
            {
                const int g = row & 7, hm = (row >> 3) & 1, mt = row >> 4;
                const int idx  = (hm + 2 * hk) ^ ks;
                const int base = (ks * 8 + mt) * 128 + idx;
                bf16_split2(pa[i].x, pa[i].y, h2, l2);
                int sl = g * 4 + t0;  int sp = sl ^ ((sl >> 3) & 1);
                AH[base + sp * 4] = h2;  AL[base + sp * 4] = l2;
                bf16_split2(pa[i].z, pa[i].w, h2, l2);
                sl = g * 4 + t0 + 1;  sp = sl ^ ((sl >> 3) & 1);
                AH[base + sp * 4] = h2;  AL[base + sp * 4] = l2;
            }
            {
                const int gn = row & 7, nt = row >> 3;
                const int base = (ks * 16 + nt) * 64 + hk;
                bf16_split2(pw[i].x, pw[i].y, h2, l2);
                int sl = gn * 4 + t0;
                int sp = (sl ^ ((sl >> 3) & 1)) ^ (ks << 3);
                BH[base + sp * 2] = h2;  BL[base + sp * 2] = l2;
                bf16_split2(pw[i].z, pw[i].w, h2, l2);
                sl = gn * 4 + t0 + 1;
                sp = (sl ^ ((sl >> 3) & 1)) ^ (ks << 3);
                BH[base + sp * 2] = h2;  BL[base + sp * 2] = l2;
            }
        }
        __syncthreads();

        if (s + 1 < NSLAB) {
            const int k0 = (s + 1) * 32;
            #pragma unroll
            for (int i = 0; i < 4; i++) {
                const int f = i * 256 + tid;
                const int row = f >> 3, k4 = (f & 7) * 4;
                pa[i] = *(const float4*)(A + (size_t)(m0 + row) * EMBED + k0 + k4);
                pw[i] = *(const float4*)(W + (size_t)(n0 + row) * EMBED + k0 + k4);
            }
        }

        const int lp = lane ^ ((lane >> 3) & 1);
        #pragma unroll
        for (int ks = 0; ks < 2; ks++) {
            uint4 ah[4], al4[4];
            uint2 bh[4], bl4[4];
            #pragma unroll
            for (int mt = 0; mt < 4; mt++) {
                const int off = (ks * 8 + wr * 4 + mt) * 128 + lp * 4;
                ah[mt]  = *(const uint4*)&AH[off];
                al4[mt] = *(const uint4*)&AL[off];
            }
            const int lpb = lp ^ (ks << 3);
            #pragma unroll
            for (int nt = 0; nt < 4; nt++) {
                const int off = (ks * 16 + wc * 4 + nt) * 64 + lpb * 2;
                bh[nt]  = *(const uint2*)&BH[off];
                bl4[nt] = *(const uint2*)&BL[off];
            }
            #pragma unroll
            for (int mt = 0; mt < 4; mt++) {
                const uint32_t a0 = ks ? ah[mt].y  : ah[mt].x;
                const uint32_t a1 = ks ? ah[mt].x  : ah[mt].y;
                const uint32_t a2 = ks ? ah[mt].w  : ah[mt].z;
                const uint32_t a3 = ks ? ah[mt].z  : ah[mt].w;
                const uint32_t e0 = ks ? al4[mt].y : al4[mt].x;
                const uint32_t e1 = ks ? al4[mt].x : al4[mt].y;
                const uint32_t e2 = ks ? al4[mt].w : al4[mt].z;
                const uint32_t e3 = ks ? al4[mt].z : al4[mt].w;
                #pragma unroll
                for (int nt = 0; nt < 4; nt++) {
                    mma_bf16(C[mt][nt], a0, a1, a2, a3, bh[nt].x, bh[nt].y);
                    mma_bf16(C[mt][nt], e0, e1, e2, e3, bh[nt].x, bh[nt].y);
                    mma_bf16(C[mt][nt], a0, a1, a2, a3, bl4[nt].x, bl4[nt].y);
                }
            }
        }
    }
}

__global__ __launch_bounds__(256) void qkv_mma_kernel(
    const float* __restrict__ x,
    const float* __restrict__ Wq, const float* __restrict__ bq,
    const float* __restrict__ Wk, const float* __restrict__ bk,
    const float* __restrict__ Wv, const float* __restrict__ bv)
{
    const float* W; const float* bias; float* dst;
    if (blockIdx.z == 0)      { W = Wq; bias = bq; dst = g_q; }
    else if (blockIdx.z == 1) { W = Wk; bias = bk; dst = g_k; }
    else                      { W = Wv; bias = bv; dst = g_v; }

    const int m0 = blockIdx.y * 128;
    const int n0 = blockIdx.x * 128;

    float C[4][4][4];
    #pragma unroll
    for (int mt = 0; mt < 4; mt++)
        #pragma unroll
        for (int nt = 0; nt < 4; nt++)
            #pragma unroll
            for (int q = 0; q < 4; q++) C[mt][nt][q] = 0.f;

    mma_gemm_mainloop(x, W, m0, n0, C);

    const int lane = threadIdx.x & 31;
    const int wid  = threadIdx.x >> 5;
    const int wr = wid >> 2, wc = wid & 3;
    const int g = lane >> 2, t = lane & 3;
    #pragma unroll
    for (int mt = 0; mt < 4; mt++) {
        #pragma unroll
        for (int nt = 0; nt < 4; nt++) {
            const int c = n0 + wc * 32 + nt * 8 + t * 2;
            const int h = c >> 6, d = c & 63;
            const float2 bv2 = *(const float2*)(bias + c);
            #pragma unroll
            for (int half = 0; half < 2; half++) {
                const int m = m0 + wr * 64 + mt * 16 + g + half * 8;
                const int b = m >> 11;
                const int n = m & 2047;
                float2 o;
                o.x = C[mt][nt][half * 2 + 0] + bv2.x;
                o.y = C[mt][nt][half * 2 + 1] + bv2.y;
                *(float2*)&dst[(((size_t)(b * NH + h) * SEQ) + n) * HD + d] = o;
            }
        }
    }
}

__global__ __launch_bounds__(256) void out_mma_kernel(
    const float* __restrict__ Wo, const float* __restrict__ bo,
    float* __restrict__ out)
{
    const int m0 = blockIdx.y * 128;
    const int n0 = blockIdx.x * 128;

    float C[4][4][4];
    #pragma unroll
    for (int mt = 0; mt < 4; mt++)
        #pragma unroll
        for (int nt = 0; nt < 4; nt++)
            #pragma unroll
            for (int q = 0; q < 4; q++) C[mt][nt][q] = 0.f;

    mma_gemm_mainloop(g_ctx, Wo, m0, n0, C);

    const int lane = threadIdx.x & 31;
    const int wid  = threadIdx.x >> 5;
    const int wr = wid >> 2, wc = wid & 3;
    const int g = lane >> 2, t = lane & 3;
    #pragma unroll
    for (int mt = 0; mt < 4; mt++) {
        #pragma unroll
        for (int nt = 0; nt < 4; nt++) {
            const int c = n0 + wc * 32 + nt * 8 + t * 2;
            const float2 bv2 = *(const float2*)(bo + c);
            #pragma unroll
            for (int half = 0; half < 2; half++) {
                const int m = m0 + wr * 64 + mt * 16 + g + half * 8;
                float2 o;
                o.x = C[mt][nt][half * 2 + 0] + bv2.x;
                o.y = C[mt][nt][half * 2 + 1] + bv2.y;
                *(float2*)&out[(size_t)m * EMBED + c] = o;
            }
        }
    }
}

// ---------------------------------------------------------------------------
// Flash attention on mma.sync bf16 with 2-term compensation.
// Block = (b*h, 64 q-rows). 256 threads = 8 warps: wr=wid>>1 (16-row slab),
// wc=wid&1 (32-col half). Tiles BC=64; S and PV each 48 mma/warp/tile.
// Q staged once (A-frag, idx^ks perm); K per tile (B-frag); V per tile
// (B-frag transposed: k=c pairs from row-pairs, ^nt slot XOR); P written
// from softmax C-frags as STS.128 at slot=lane (C/A lane maps coincide).
// Row stats reduced across the wc pair via named barriers (bar.sync 1+wr,64).
// ---------------------------------------------------------------------------
// smem (u32 units): QH 2048 | QL 2048 | KH 2048 | KL 2048 | VH 2048 | VL 2048
//                   | PH 2048 | PL 2048 | smax 128 | ssum 128
#define ATT_SMEM ((8*2048 + 256) * 4)   // 66560 bytes

__global__ __launch_bounds__(256) void attn_kernel()
{
    extern __shared__ uint32_t smu[];
    uint32_t* QH = smu;
    uint32_t* QL = smu + 2048;
    uint32_t* KH = smu + 4096;
    uint32_t* KL = smu + 6144;
    uint32_t* VH = smu + 8192;
    uint32_t* VL = smu + 10240;
    uint32_t* PH = smu + 12288;
    uint32_t* PL = smu + 14336;
    float* smax  = (float*)(smu + 16384);   // [2][64]
    float* ssum  = smax + 128;              // [2][64]

    const int tid  = threadIdx.x;
    const int lane = tid & 31;
    const int wid  = tid >> 5;
    const int wr   = wid >> 1;       // 0..3: 16-row slab
    const int wc   = wid & 1;        // 0..1: 32-col half
    const int g    = lane >> 2;
    const int t    = lane & 3;
    const int lp   = lane ^ ((lane >> 3) & 1);

    const int bh = blockIdx.y;
    const int q0 = blockIdx.x * 64;
    const size_t gbase = (size_t)bh * SEQ * HD;
    const float* Qg = g_q + gbase;
    const float* Kg = g_k + gbase;
    const float* Vg = g_v + gbase;

    // ---- stage Q once (A-frag layout, 0.125 scale folded in) ----
    #pragma unroll
    for (int it = 0; it < 4; it++) {
        const int f  = it * 256 + tid;
        const int r  = f >> 4;
        const int dq = (f & 15) * 4;
        float4 v = *(const float4*)(Qg + (size_t)(q0 + r) * HD + dq);
        v.x *= 0.125f; v.y *= 0.125f; v.z *= 0.125f; v.w *= 0.125f;
        const int mt = r >> 4, row = r & 15;
        const int gg = row & 7, hm = row >> 3;
        const int ks = dq >> 4, kk = dq & 15;
        const int khalf = kk >> 3, t0 = (kk & 7) >> 1;
        const int idx  = (hm + 2 * khalf) ^ ks;
        const int base = (ks * 4 + mt) * 128 + idx;
        uint32_t h2, l2;
        bf16_split2(v.x, v.y, h2, l2);
        int sl = gg * 4 + t0;  int sp = sl ^ ((sl >> 3) & 1);
        QH[base + sp * 4] = h2;  QL[base + sp * 4] = l2;
        bf16_split2(v.z, v.w, h2, l2);
        sl = gg * 4 + t0 + 1;  sp = sl ^ ((sl >> 3) & 1);
        QH[base + sp * 4] = h2;  QL[base + sp * 4] = l2;
    }

    float O[4][4];
    #pragma unroll
    for (int nt = 0; nt < 4; nt++)
        #pragma unroll
        for (int q = 0; q < 4; q++) O[nt][q] = 0.f;
    float mrow0 = -1e30f, mrow1 = -1e30f, lsum0 = 0.f, lsum1 = 0.f;

    #pragma unroll 1
    for (int kt = 0; kt < SEQ / 64; kt++) {
        const int ct = kt * 64;
        __syncthreads();    // prev tile's mma done before restage

        // ---- stage K (B-frag) ----
        #pragma unroll
        for (int it = 0; it < 4; it++) {
            const int f  = it * 256 + tid;
            const int r  = f >> 4;
            const int k4 = (f & 15) * 4;
            float4 v = *(const float4*)(Kg + (size_t)(ct + r) * HD + k4);
            const int nt = r >> 3, gn = r & 7;
            const int ks = k4 >> 4, kk = k4 & 15;
            const int khalf = kk >> 3, t0 = (kk & 7) >> 1;
            const int base = (ks * 8 + nt) * 64 + khalf;
            uint32_t h2, l2;
            bf16_split2(v.x, v.y, h2, l2);
            int sl = gn * 4 + t0;
            int sp = (sl ^ ((sl >> 3) & 1)) ^ (ks << 3);
            KH[base + sp * 2] = h2;  KL[base + sp * 2] = l2;
            bf16_split2(v.z, v.w, h2, l2);
            sl = gn * 4 + t0 + 1;
            sp = (sl ^ ((sl >> 3) & 1)) ^ (ks << 3);
            KH[base + sp * 2] = h2;  KL[base + sp * 2] = l2;
        }
        // ---- stage V transposed (B-frag, k=c from row pairs) ----
        #pragma unroll
        for (int it = 0; it < 2; it++) {
            const int f  = it * 256 + tid;
            const int cp = f >> 4;
            const int dq = (f & 15) * 4;
            const int c0 = cp * 2;
            float4 v0 = *(const float4*)(Vg + (size_t)(ct + c0)     * HD + dq);
            float4 v1 = *(const float4*)(Vg + (size_t)(ct + c0 + 1) * HD + dq);
            const int ks = c0 >> 4, kc = c0 & 15;
            const int khalf = kc >> 3, tt = (kc & 7) >> 1;
            const float* a0 = (const float*)&v0;
            const float* a1 = (const float*)&v1;
            #pragma unroll
            for (int j = 0; j < 4; j++) {
                const int d = dq + j;
                const int nt = d >> 3, gn = d & 7;
                const int sl = gn * 4 + tt;
                const int sp = ((sl ^ ((sl >> 3) & 1)) ^ (ks << 3)) ^ nt;
                const int addr = (ks * 8 + nt) * 64 + khalf + sp * 2;
                uint32_t h2, l2;
                bf16_split2(a0[j], a1[j], h2, l2);
                VH[addr] = h2;  VL[addr] = l2;
            }
        }
        __syncthreads();

        // ---- S = Q K^T (3-term compensated) ----
        float sS[4][4];
        #pragma unroll
        for (int nt = 0; nt < 4; nt++)
            #pragma unroll
            for (int q = 0; q < 4; q++) sS[nt][q] = 0.f;

        #pragma unroll
        for (int ks = 0; ks < 4; ks++) {
            uint4 qh4 = *(const uint4*)&QH[(ks * 4 + wr) * 128 + lp * 4];
            uint4 ql4 = *(const uint4*)&QL[(ks * 4 + wr) * 128 + lp * 4];
            const uint32_t* qh = (const uint32_t*)&qh4;
            const uint32_t* ql = (const uint32_t*)&ql4;
            const uint32_t a0 = qh[0 ^ ks], a1 = qh[1 ^ ks];
            const uint32_t a2 = qh[2 ^ ks], a3 = qh[3 ^ ks];
            const uint32_t e0 = ql[0 ^ ks], e1 = ql[1 ^ ks];
            const uint32_t e2 = ql[2 ^ ks], e3 = ql[3 ^ ks];
            const int lpb = lp ^ (ks << 3);
            #pragma unroll
            for (int ntl = 0; ntl < 4; ntl++) {
                const int nt = wc * 4 + ntl;
                uint2 kh = *(const uint2*)&KH[(ks * 8 + nt) * 64 + lpb * 2];
                uint2 kl = *(const uint2*)&KL[(ks * 8 + nt) * 64 + lpb * 2];
                mma_bf16(sS[ntl], a0, a1, a2, a3, kh.x, kh.y);
                mma_bf16(sS[ntl], e0, e1, e2, e3, kh.x, kh.y);
                mma_bf16(sS[ntl], a0, a1, a2, a3, kl.x, kl.y);
            }
        }

        // ---- online softmax (rows g / g+8 of slab wr; pair reduction) ----
        float mx0 = fmaxf(fmaxf(sS[0][0], sS[0][1]), fmaxf(sS[1][0], sS[1][1]));
        mx0 = fmaxf(mx0, fmaxf(fmaxf(sS[2][0], sS[2][1]), fmaxf(sS[3][0], sS[3][1])));
        float mx1 = fmaxf(fmaxf(sS[0][2], sS[0][3]), fmaxf(sS[1][2], sS[1][3]));
        mx1 = fmaxf(mx1, fmaxf(fmaxf(sS[2][2], sS[2][3]), fmaxf(sS[3][2], sS[3][3])));
        mx0 = fmaxf(mx0, __shfl_xor_sync(0xffffffffu, mx0, 1, 32));
        mx0 = fmaxf(mx0, __shfl_xor_sync(0xffffffffu, mx0, 2, 32));
        mx1 = fmaxf(mx1, __shfl_xor_sync(0xffffffffu, mx1, 1, 32));
        mx1 = fmaxf(mx1, __shfl_xor_sync(0xffffffffu, mx1, 2, 32));
        const int r0l = wr * 16 + g;           // local row of row g
        if (t == 0) {
            smax[wc * 64 + r0l]     = mx0;
            smax[wc * 64 + r0l + 8] = mx1;
        }
        BAR_PAIR(1 + wr);
        const float M0 = fmaxf(smax[r0l],     smax[64 + r0l]);
        const float M1 = fmaxf(smax[r0l + 8], smax[64 + r0l + 8]);
        const float mn0 = fmaxf(mrow0, M0), mn1 = fmaxf(mrow1, M1);
        const float cr0 = __expf(mrow0 - mn0), cr1 = __expf(mrow1 - mn1);
        mrow0 = mn0;  mrow1 = mn1;

        float rs0 = 0.f, rs1 = 0.f;
        #pragma unroll
        for (int nt = 0; nt < 4; nt++) {
            sS[nt][0] = __expf(sS[nt][0] - mn0);
            sS[nt][1] = __expf(sS[nt][1] - mn0);
            sS[nt][2] = __expf(sS[nt][2] - mn1);
            sS[nt][3] = __expf(sS[nt][3] - mn1);
            rs0 += sS[nt][0] + sS[nt][1];
            rs1 += sS[nt][2] + sS[nt][3];
        }
        rs0 += __shfl_xor_sync(0xffffffffu, rs0, 1, 32);
        rs0 += __shfl_xor_sync(0xffffffffu, rs0, 2, 32);
        rs1 += __shfl_xor_sync(0xffffffffu, rs1, 1, 32);
        rs1 += __shfl_xor_sync(0xffffffffu, rs1, 2, 32);
        if (t == 0) {
            ssum[wc * 64 + r0l]     = rs0;
            ssum[wc * 64 + r0l + 8] = rs1;
        }
        BAR_PAIR(1 + wr);
        lsum0 = lsum0 * cr0 + ssum[r0l]     + ssum[64 + r0l];
        lsum1 = lsum1 * cr1 + ssum[r0l + 8] + ssum[64 + r0l + 8];

        // rescale O by corr
        #pragma unroll
        for (int nt = 0; nt < 4; nt++) {
            O[nt][0] *= cr0;  O[nt][1] *= cr0;
            O[nt][2] *= cr1;  O[nt][3] *= cr1;
        }

        // ---- stage P from C-frags (A-frag layout, STS.128 at slot=lane) ----
        #pragma unroll
        for (int kl = 0; kl < 2; kl++) {
            const int ks = wc * 2 + kl;
            uint4 hh, ll;
            bf16_split2(sS[2*kl][0],   sS[2*kl][1],   hh.x, ll.x);
            bf16_split2(sS[2*kl][2],   sS[2*kl][3],   hh.y, ll.y);
            bf16_split2(sS[2*kl+1][0], sS[2*kl+1][1], hh.z, ll.z);
            bf16_split2(sS[2*kl+1][2], sS[2*kl+1][3], hh.w, ll.w);
            *(uint4*)&PH[(ks * 4 + wr) * 128 + lane * 4] = hh;
            *(uint4*)&PL[(ks * 4 + wr) * 128 + lane * 4] = ll;
        }
        BAR_PAIR(1 + wr);

        // ---- O += P V (3-term compensated) ----
        #pragma unroll
        for (int ks = 0; ks < 4; ks++) {
            uint4 ph4 = *(const uint4*)&PH[(ks * 4 + wr) * 128 + lane * 4];
            uint4 pl4 = *(const uint4*)&PL[(ks * 4 + wr) * 128 + lane * 4];
            #pragma unroll
            for (int ntl = 0; ntl < 4; ntl++) {
                const int nt = wc * 4 + ntl;
                const int lpv = (lp ^ (ks << 3)) ^ nt;
                uint2 vh = *(const uint2*)&VH[(ks * 8 + nt) * 64 + lpv * 2];
                uint2 vl = *(const uint2*)&VL[(ks * 8 + nt) * 64 + lpv * 2];
                mma_bf16(O[ntl], ph4.x, ph4.y, ph4.z, ph4.w, vh.x, vh.y);
                mma_bf16(O[ntl], pl4.x, pl4.y, pl4.z, pl4.w, vh.x, vh.y);
                mma_bf16(O[ntl], ph4.x, ph4.y, ph4.z, ph4.w, vl.x, vl.y);
            }
        }
    }

    // ---- normalize + write context [B,N,C] (c = h*64 + d) ----
    const int b = bh / NH, h = bh % NH;
    const float inv0 = 1.0f / lsum0, inv1 = 1.0f / lsum1;
    #pragma unroll
    for (int ntl = 0; ntl < 4; ntl++) {
        const int d = wc * 32 + ntl * 8 + t * 2;
        const int r0 = q0 + wr * 16 + g;
        float2 o0 = make_float2(O[ntl][0] * inv0, O[ntl][1] * inv0);
        float2 o1 = make_float2(O[ntl][2] * inv1, O[ntl][3] * inv1);
        *(float2*)&g_ctx[((size_t)(b * SEQ + r0))     * EMBED + h * HD + d] = o0;
        *(float2*)&g_ctx[((size_t)(b * SEQ + r0 + 8)) * EMBED + h * HD + d] = o1;
    }
}

// ---------------------------------------------------------------------------
extern "C" void kernel_launch(void* const* d_in, const int* in_sizes, int n_in,
                              void* d_out, int out_size)
{
    const float* x  = (const float*)d_in[0];
    const float* Wq = (const float*)d_in[1];
    const float* bq = (const float*)d_in[2];
    const float* Wk = (const float*)d_in[3];
    const float* bk = (const float*)d_in[4];
    const float* Wv = (const float*)d_in[5];
    const float* bv = (const float*)d_in[6];
    const float* Wo = (const float*)d_in[7];
    const float* bo = (const float*)d_in[8];
    float* out = (float*)d_out;

    cudaFuncSetAttribute(attn_kernel,
                         cudaFuncAttributeMaxDynamicSharedMemorySize, ATT_SMEM);

    dim3 gq(EMBED/128, MROWS/128, 3);   // (6, 64, 3)
    qkv_mma_kernel<<<gq, 256>>>(x, Wq, bq, Wk, bk, Wv, bv);

    dim3 ga(SEQ/64, BATCH*NH);          // (32, 48)
    attn_kernel<<<ga, 256, ATT_SMEM>>>();

    dim3 go(EMBED/128, MROWS/128);      // (6, 64)
    out_mma_kernel<<<go, 256>>>(Wo, bo, out);
}